// round 16
// baseline (speedup 1.0000x reference)
#include <cuda_runtime.h>
#include <cuda_bf16.h>
#include <math.h>

// Problem dims
#define B_ 8
#define L_ 512
#define D_ 512
#define H_ 8
#define DH_ 64
#define NROWS 4096          // B*L
#define NPAD 1664           // 13*128 GEMM N (q512|k512|v512|p24|pad)
#define KPB 1024            // B2T k extent: [hi(512) | lo(512)]

// Output layout (concatenated fp32): readout | state_seq | mom_seq
#define OFF_S 2097152UL
#define OFF_M 136314880UL

// Packed per-(b,h) stream: [q(64) | k_norm(64) | v(64) | a,e,th,pad] per step
#define PSTEP 196

// Scratch (static device arrays — no allocation)
__device__ __nv_bfloat16 g_B2T[(size_t)NPAD * KPB]; // n-major: [Whi | Wlo]
__device__ float g_pack[(size_t)B_ * H_ * L_ * PSTEP];

// ---------------------------------------------------------------------------
// Kernel 1: split + transpose weights -> B2T bf16 [1664 (n), 1024 (k)]
// Tiled transpose through smem (coalesced both sides).
// ---------------------------------------------------------------------------
__global__ __launch_bounds__(256) void pack_b2t_kernel(const float* __restrict__ Wq,
                                                       const float* __restrict__ Wk,
                                                       const float* __restrict__ Wv,
                                                       const float* __restrict__ Wp) {
    __shared__ float tile[32][33];
    const int n0 = blockIdx.x * 32;
    const int k0 = blockIdx.y * 32;
    const int tx = threadIdx.x;
    const int ty = threadIdx.y;

#pragma unroll
    for (int i = 0; i < 4; i++) {
        int k = k0 + ty + i * 8;
        int n = n0 + tx;
        float x = 0.f;
        if (n < 512)       x = Wq[k * 512 + n];
        else if (n < 1024) x = Wk[k * 512 + (n - 512)];
        else if (n < 1536) x = Wv[k * 512 + (n - 1024)];
        else if (n < 1560) x = Wp[k * 24 + (n - 1536)];
        tile[ty + i * 8][tx] = x;
    }
    __syncthreads();

#pragma unroll
    for (int i = 0; i < 4; i++) {
        int n = n0 + ty + i * 8;
        int k = k0 + tx;
        float x = tile[tx][ty + i * 8];
        __nv_bfloat16 hi = __float2bfloat16_rn(x);
        __nv_bfloat16 lo = __float2bfloat16_rn(x - __bfloat162float(hi));
        __nv_bfloat16* base = g_B2T + (size_t)n * KPB;
        base[k]       = hi;
        base[512 + k] = lo;
    }
}

// ---------------------------------------------------------------------------
// Kernel 2: bf16 tensor-core GEMM, split precision, fully fused epilogue.
// C = Ahi*Whi + Ahi*Wlo + Alo*Whi over K=512 (A converted fp32->hi/lo in the
// loader; no packed-A intermediate). 128x128 CTA tile, 8 warps (4m x 2n),
// warp tile 32m x 64n = one head per warp n-span.
// Epilogue: q/v -> g_pack; k -> L2-normalized -> g_pack; p-tile -> gate
// activations (sigmoid/softplus + bias) -> g_pack. No scratch round-trips.
// ---------------------------------------------------------------------------
#define SSTR 24
__device__ __forceinline__ unsigned pack_bf2(float x, float y) {
    __nv_bfloat162 t = __floats2bfloat162_rn(x, y);
    return *(unsigned*)&t;
}

__global__ __launch_bounds__(256) void mma_gemm_kernel(const float* __restrict__ A,
                                                       const float* __restrict__ bp) {
    __shared__ __align__(16) __nv_bfloat16 Ah[128 * SSTR];
    __shared__ __align__(16) __nv_bfloat16 Al[128 * SSTR];
    __shared__ __align__(16) __nv_bfloat16 Bh[128 * SSTR];
    __shared__ __align__(16) __nv_bfloat16 Bl[128 * SSTR];
    const int tid  = threadIdx.x;
    const int lane = tid & 31;
    const int wid  = tid >> 5;
    const int wm   = wid >> 1;
    const int wn   = wid & 1;
    const int m0   = blockIdx.y * 128;
    const int n0   = blockIdx.x * 128;
    const int r    = lane >> 2;
    const int cq   = (lane & 3) * 2;

    float acc[2][8][4];
#pragma unroll
    for (int mt = 0; mt < 2; mt++)
#pragma unroll
        for (int nt = 0; nt < 8; nt++)
#pragma unroll
            for (int u = 0; u < 4; u++) acc[mt][nt][u] = 0.f;

    // loaders: thread covers row lr, k-span lh..lh+7
    const int lr = tid >> 1;
    const int lh = (tid & 1) * 8;
    const float* gA = A + (size_t)(m0 + lr) * D_ + lh;
    const __nv_bfloat16* gBh = g_B2T + (size_t)(n0 + lr) * KPB + lh;
    const __nv_bfloat16* gBl = gBh + 512;

    float4 av0 = *(const float4*)gA;
    float4 av1 = *(const float4*)(gA + 4);
    uint4 bvh = *(const uint4*)gBh;
    uint4 bvl = *(const uint4*)gBl;

    for (int k0 = 0; k0 < D_; k0 += 16) {
        __syncthreads();
        // convert A fp32 -> hi/lo and store; store B hi/lo
        {
            float xs[8] = {av0.x, av0.y, av0.z, av0.w, av1.x, av1.y, av1.z, av1.w};
            unsigned hi[4], lo[4];
#pragma unroll
            for (int i = 0; i < 4; i++) {
                float x = xs[2 * i], y = xs[2 * i + 1];
                __nv_bfloat16 hx = __float2bfloat16_rn(x);
                __nv_bfloat16 hy = __float2bfloat16_rn(y);
                hi[i] = pack_bf2(__bfloat162float(hx), __bfloat162float(hy)); // exact repack
                lo[i] = pack_bf2(x - __bfloat162float(hx), y - __bfloat162float(hy));
            }
            *(uint4*)&Ah[lr * SSTR + lh] = make_uint4(hi[0], hi[1], hi[2], hi[3]);
            *(uint4*)&Al[lr * SSTR + lh] = make_uint4(lo[0], lo[1], lo[2], lo[3]);
            *(uint4*)&Bh[lr * SSTR + lh] = bvh;
            *(uint4*)&Bl[lr * SSTR + lh] = bvl;
        }
        __syncthreads();

        if (k0 + 16 < D_) {
            av0 = *(const float4*)(gA + k0 + 16);
            av1 = *(const float4*)(gA + k0 + 20);
            bvh = *(const uint4*)(gBh + k0 + 16);
            bvl = *(const uint4*)(gBl + k0 + 16);
        }

        unsigned bh0[8], bh1[8], bl0[8], bl1[8];
#pragma unroll
        for (int nt = 0; nt < 8; nt++) {
            int n = wn * 64 + nt * 8 + r;
            bh0[nt] = *(const unsigned*)&Bh[n * SSTR + cq];
            bh1[nt] = *(const unsigned*)&Bh[n * SSTR + cq + 8];
            bl0[nt] = *(const unsigned*)&Bl[n * SSTR + cq];
            bl1[nt] = *(const unsigned*)&Bl[n * SSTR + cq + 8];
        }
#pragma unroll
        for (int mt = 0; mt < 2; mt++) {
            int m = wm * 32 + mt * 16 + r;
            unsigned ah0 = *(const unsigned*)&Ah[m * SSTR + cq];
            unsigned ah1 = *(const unsigned*)&Ah[(m + 8) * SSTR + cq];
            unsigned ah2 = *(const unsigned*)&Ah[m * SSTR + cq + 8];
            unsigned ah3 = *(const unsigned*)&Ah[(m + 8) * SSTR + cq + 8];
            unsigned al0 = *(const unsigned*)&Al[m * SSTR + cq];
            unsigned al1 = *(const unsigned*)&Al[(m + 8) * SSTR + cq];
            unsigned al2 = *(const unsigned*)&Al[m * SSTR + cq + 8];
            unsigned al3 = *(const unsigned*)&Al[(m + 8) * SSTR + cq + 8];
#pragma unroll
            for (int nt = 0; nt < 8; nt++) {
                // Ahi * Bhi
                asm volatile(
                    "mma.sync.aligned.m16n8k16.row.col.f32.bf16.bf16.f32 "
                    "{%0,%1,%2,%3}, {%4,%5,%6,%7}, {%8,%9}, {%0,%1,%2,%3};"
                    : "+f"(acc[mt][nt][0]), "+f"(acc[mt][nt][1]),
                      "+f"(acc[mt][nt][2]), "+f"(acc[mt][nt][3])
                    : "r"(ah0), "r"(ah1), "r"(ah2), "r"(ah3),
                      "r"(bh0[nt]), "r"(bh1[nt]));
                // Ahi * Blo
                asm volatile(
                    "mma.sync.aligned.m16n8k16.row.col.f32.bf16.bf16.f32 "
                    "{%0,%1,%2,%3}, {%4,%5,%6,%7}, {%8,%9}, {%0,%1,%2,%3};"
                    : "+f"(acc[mt][nt][0]), "+f"(acc[mt][nt][1]),
                      "+f"(acc[mt][nt][2]), "+f"(acc[mt][nt][3])
                    : "r"(ah0), "r"(ah1), "r"(ah2), "r"(ah3),
                      "r"(bl0[nt]), "r"(bl1[nt]));
                // Alo * Bhi
                asm volatile(
                    "mma.sync.aligned.m16n8k16.row.col.f32.bf16.bf16.f32 "
                    "{%0,%1,%2,%3}, {%4,%5,%6,%7}, {%8,%9}, {%0,%1,%2,%3};"
                    : "+f"(acc[mt][nt][0]), "+f"(acc[mt][nt][1]),
                      "+f"(acc[mt][nt][2]), "+f"(acc[mt][nt][3])
                    : "r"(al0), "r"(al1), "r"(al2), "r"(al3),
                      "r"(bh0[nt]), "r"(bh1[nt]));
            }
        }
    }

    // ---------------- fused epilogue ----------------
    const int nx = blockIdx.x;
    if (nx < 12) {
        const int region = nx >> 2;               // 0=q, 1=k, 2=v
        const int off    = region * 64;
        const int h      = (nx & 3) * 2 + wn;

#pragma unroll
        for (int mt = 0; mt < 2; mt++) {
            const int mA = m0 + wm * 32 + mt * 16 + r;
            const int mB = mA + 8;

            float sc0 = 1.f, sc1 = 1.f;
            if (region == 1) {
                float ss0 = 0.f, ss1 = 0.f;
#pragma unroll
                for (int nt = 0; nt < 8; nt++) {
                    ss0 = fmaf(acc[mt][nt][0], acc[mt][nt][0], ss0);
                    ss0 = fmaf(acc[mt][nt][1], acc[mt][nt][1], ss0);
                    ss1 = fmaf(acc[mt][nt][2], acc[mt][nt][2], ss1);
                    ss1 = fmaf(acc[mt][nt][3], acc[mt][nt][3], ss1);
                }
                ss0 += __shfl_xor_sync(0xffffffffu, ss0, 1);
                ss1 += __shfl_xor_sync(0xffffffffu, ss1, 1);
                ss0 += __shfl_xor_sync(0xffffffffu, ss0, 2);
                ss1 += __shfl_xor_sync(0xffffffffu, ss1, 2);
                sc0 = 1.0f / fmaxf(sqrtf(ss0), 1e-12f);
                sc1 = 1.0f / fmaxf(sqrtf(ss1), 1e-12f);
            }

            const int bA = mA >> 9, lA = mA & 511;
            const int bB = mB >> 9, lB = mB & 511;
            float* dA = g_pack + ((size_t)(bA * 8 + h) * 512 + lA) * PSTEP + off + cq;
            float* dB = g_pack + ((size_t)(bB * 8 + h) * 512 + lB) * PSTEP + off + cq;
#pragma unroll
            for (int nt = 0; nt < 8; nt++) {
                *(float2*)(dA + nt * 8) = make_float2(acc[mt][nt][0] * sc0,
                                                      acc[mt][nt][1] * sc0);
                *(float2*)(dB + nt * 8) = make_float2(acc[mt][nt][2] * sc1,
                                                      acc[mt][nt][3] * sc1);
            }
        }
    } else {
        // p tile: gate activations fused here. cols cp = nt*8+cq < 24 (wn==0).
        if (wn == 0) {
#pragma unroll
            for (int mt = 0; mt < 2; mt++) {
                const int mA = m0 + wm * 32 + mt * 16 + r;
                const int mB = mA + 8;
                const int bA = mA >> 9, lA = mA & 511;
                const int bB = mB >> 9, lB = mB & 511;
#pragma unroll
                for (int nt = 0; nt < 3; nt++) {
                    const int cp = nt * 8 + cq;       // 0..22, even; cp+1 <= 23
                    const float b0 = bp[cp], b1 = bp[cp + 1];
#pragma unroll
                    for (int half = 0; half < 2; half++) {
                        const int cc   = cp + half;
                        const int slot = cc >> 3;     // 0=alpha,1=eta,2=theta
                        const int h    = cc & 7;
                        const float bb = half ? b1 : b0;
                        float pA = acc[mt][nt][half]     + bb;
                        float pB = acc[mt][nt][2 + half] + bb;
                        float gA_, gB_;
                        if (slot < 2) {
                            gA_ = 1.0f / (1.0f + expf(-pA));
                            gB_ = 1.0f / (1.0f + expf(-pB));
                        } else {
                            gA_ = (pA > 20.f) ? pA : log1pf(expf(pA));
                            gB_ = (pB > 20.f) ? pB : log1pf(expf(pB));
                        }
                        g_pack[((size_t)(bA * 8 + h) * 512 + lA) * PSTEP + 192 + slot] = gA_;
                        g_pack[((size_t)(bB * 8 + h) * 512 + lB) * PSTEP + 192 + slot] = gB_;
                    }
                }
            }
        }
    }
}

// ---------------------------------------------------------------------------
// Kernel 3: recurrence (r12-proven config, STG stores).
// grid = B*H*16 = 1024 CTAs x 64 threads (2048 warps).
// CTA handles 4 rows of one (b,h). Thread (r = t>>4, c = t&15) owns 4 cols.
// 4-deep register ring with prefetch distance 3 to cover L2/DRAM latency.
// ---------------------------------------------------------------------------
__global__ __launch_bounds__(64) void recurrence_kernel(const float* __restrict__ prev_state,
                                                        const float* __restrict__ prev_mom,
                                                        float* __restrict__ out) {
    const int bid = blockIdx.x;
    const int rb  = bid & 15;
    const int h   = (bid >> 4) & 7;
    const int b   = bid >> 7;
    const int t   = threadIdx.x;
    const int r = t >> 4, c = t & 15;
    const int gi = rb * 4 + r;                  // global state row in [0,64)

    float s[4], m[4];
    {
        const size_t off = ((size_t)((b * 8 + h) * 64 + gi)) * 64 + c * 4;
        *(float4*)&s[0] = *(const float4*)(prev_state + off);
        *(float4*)&m[0] = *(const float4*)(prev_mom + off);
    }

    const float* pbh = g_pack + (size_t)((b * 8 + h) * 512) * PSTEP;
    float* ro  = out + ((size_t)(b * 512) * 8 + h) * 64 + gi;
    float* ssq = out + OFF_S + ((size_t)(b * 512) * 8 + h) * 4096 + (size_t)gi * 64 + c * 4;
    float* msq = ssq + (OFF_M - OFF_S);

    // 4-deep prefetch ring (q, k, v, gates)
    float qb[4][4], kb[4][4], vb[4];
    float4 gb[4];
#pragma unroll
    for (int p = 0; p < 3; p++) {
        const float* sp = pbh + p * PSTEP;
        *(float4*)qb[p] = *(const float4*)(sp + c * 4);
        *(float4*)kb[p] = *(const float4*)(sp + 64 + c * 4);
        vb[p] = sp[128 + gi];
        gb[p] = *(const float4*)(sp + 192);
    }

#pragma unroll 4
    for (int l = 0; l < 512; ++l) {
        const int bi = l & 3;
        const int pi = (l + 3) & 3;
        const int pl = (l + 3 < 512) ? (l + 3) : 511;
        const float* sp = pbh + (size_t)pl * PSTEP;
        *(float4*)qb[pi] = *(const float4*)(sp + c * 4);
        *(float4*)kb[pi] = *(const float4*)(sp + 64 + c * 4);
        vb[pi] = sp[128 + gi];
        gb[pi] = *(const float4*)(sp + 192);

        // partial dot products over owned 4 columns
        float pv = 0.f, py = 0.f;
#pragma unroll
        for (int u = 0; u < 4; u++) {
            pv = fmaf(s[u], kb[bi][u], pv);
            py = fmaf(s[u], qb[bi][u], py);
        }
        // reduce over the 16 lanes of this row (pv/py chains interleave)
        pv += __shfl_xor_sync(0xffffffffu, pv, 1);
        py += __shfl_xor_sync(0xffffffffu, py, 1);
        pv += __shfl_xor_sync(0xffffffffu, pv, 2);
        py += __shfl_xor_sync(0xffffffffu, py, 2);
        pv += __shfl_xor_sync(0xffffffffu, pv, 4);
        py += __shfl_xor_sync(0xffffffffu, py, 4);
        pv += __shfl_xor_sync(0xffffffffu, pv, 8);
        py += __shfl_xor_sync(0xffffffffu, py, 8);

        if (c == 0) __stcs(ro + (size_t)l * 512, py);   // readout: PRE-update state

        const float d   = pv - vb[bi];
        const float td  = gb[bi].z * d;
        const float oma = 1.0f - gb[bi].x;
        const float e   = gb[bi].y;
#pragma unroll
        for (int u = 0; u < 4; u++) {
            m[u] = fmaf(e, m[u], -td * kb[bi][u]);   // eta*mom - theta*grad
            s[u] = fmaf(oma, s[u], m[u]);            // (1-alpha)*state + mom
        }

        __stcs((float4*)(ssq + (size_t)l * 32768), *(float4*)&s[0]);
        __stcs((float4*)(msq + (size_t)l * 32768), *(float4*)&m[0]);
    }
}

// ---------------------------------------------------------------------------
// Launch
// ---------------------------------------------------------------------------
extern "C" void kernel_launch(void* const* d_in, const int* in_sizes, int n_in,
                              void* d_out, int out_size) {
    const float* inputs   = (const float*)d_in[0];
    const float* Wq       = (const float*)d_in[1];
    const float* Wk       = (const float*)d_in[2];
    const float* Wv       = (const float*)d_in[3];
    const float* Wp       = (const float*)d_in[4];
    const float* bp       = (const float*)d_in[5];
    const float* prev_st  = (const float*)d_in[6];
    const float* prev_mom = (const float*)d_in[7];
    float* out = (float*)d_out;

    pack_b2t_kernel<<<dim3(NPAD / 32, D_ / 32), dim3(32, 8)>>>(Wq, Wk, Wv, Wp);
    mma_gemm_kernel<<<dim3(NPAD / 128, NROWS / 128), 256>>>(inputs, bp);
    recurrence_kernel<<<B_ * H_ * 16, 64>>>(prev_st, prev_mom, out);
}

// round 17
// speedup vs baseline: 1.0943x; 1.0943x over previous
#include <cuda_runtime.h>
#include <cuda_bf16.h>
#include <math.h>

// Problem dims
#define B_ 8
#define L_ 512
#define D_ 512
#define H_ 8
#define DH_ 64
#define NROWS 4096          // B*L
#define NPAD 1664           // 13*128 GEMM N (q512|k512|v512|p24|pad)
#define KP 1536             // split-GEMM K' = 3*512

// Output layout (concatenated fp32): readout | state_seq | mom_seq
#define OFF_S 2097152UL
#define OFF_M 136314880UL

// Packed per-(b,h) stream: [q(64) | k_norm(64) | v(64) | a,e,th,pad] per step
#define PSTEP 196

// Scratch (static device arrays — no allocation)
__device__ __nv_bfloat16 g_A2[(size_t)NROWS * KP];   // [Ahi | Ahi | Alo] rows
__device__ __nv_bfloat16 g_B2T[(size_t)NPAD * KP];   // n-major: [Whi ; Wlo ; Whi]
__device__ float g_pack[(size_t)B_ * H_ * L_ * PSTEP];

// ---------------------------------------------------------------------------
// Kernel 1a: split inputs A[4096,512] -> A2 bf16 [4096,1536]
// sections: [0,512)=hi, [512,1024)=hi, [1024,1536)=lo
// ---------------------------------------------------------------------------
__global__ void pack_a2_kernel(const float* __restrict__ A) {
    int idx = blockIdx.x * blockDim.x + threadIdx.x;
    if (idx >= NROWS * KP) return;
    int m  = idx / KP;
    int kk = idx - m * KP;
    int k  = (kk < 512) ? kk : ((kk < 1024) ? kk - 512 : kk - 1024);
    float x = A[(size_t)m * D_ + k];
    __nv_bfloat16 hi = __float2bfloat16_rn(x);
    if (kk < 1024) {
        g_A2[idx] = hi;
    } else {
        g_A2[idx] = __float2bfloat16_rn(x - __bfloat162float(hi));
    }
}

// ---------------------------------------------------------------------------
// Kernel 1b: split + transpose weights -> B2T bf16 [1664 (n), 1536 (k)]
// Tiled transpose through smem (coalesced both sides).
// k-sections: [0,512)=hi, [512,1024)=lo, [1024,1536)=hi
// ---------------------------------------------------------------------------
__global__ __launch_bounds__(256) void pack_b2t_kernel(const float* __restrict__ Wq,
                                                       const float* __restrict__ Wk,
                                                       const float* __restrict__ Wv,
                                                       const float* __restrict__ Wp) {
    __shared__ float tile[32][33];
    const int n0 = blockIdx.x * 32;
    const int k0 = blockIdx.y * 32;
    const int tx = threadIdx.x;
    const int ty = threadIdx.y;

#pragma unroll
    for (int i = 0; i < 4; i++) {
        int k = k0 + ty + i * 8;
        int n = n0 + tx;
        float x = 0.f;
        if (n < 512)       x = Wq[k * 512 + n];
        else if (n < 1024) x = Wk[k * 512 + (n - 512)];
        else if (n < 1536) x = Wv[k * 512 + (n - 1024)];
        else if (n < 1560) x = Wp[k * 24 + (n - 1536)];
        tile[ty + i * 8][tx] = x;
    }
    __syncthreads();

#pragma unroll
    for (int i = 0; i < 4; i++) {
        int n = n0 + ty + i * 8;
        int k = k0 + tx;
        float x = tile[tx][ty + i * 8];
        __nv_bfloat16 hi = __float2bfloat16_rn(x);
        __nv_bfloat16 lo = __float2bfloat16_rn(x - __bfloat162float(hi));
        __nv_bfloat16* base = g_B2T + (size_t)n * KP;
        base[k]        = hi;
        base[512 + k]  = lo;
        base[1024 + k] = hi;
    }
}

// ---------------------------------------------------------------------------
// Kernel 2: bf16 tensor-core GEMM with FULLY fused epilogue (r12 mainloop).
// C[4096,1664] = A2 @ B2. 128x128 CTA tile, 8 warps (4m x 2n), warp tile
// 32m x 64n = exactly one head per warp n-span.
// Epilogue routes directly into g_pack:
//   n-tiles 0-3: q ; 4-7: k (L2-normalized in-register) ; 8-11: v
//   n-tile 12: gate logits -> bias + sigmoid/softplus -> g_pack (no g_p)
// ---------------------------------------------------------------------------
#define SSTR 24
__global__ __launch_bounds__(256) void mma_gemm_kernel(const float* __restrict__ bp) {
    __shared__ __align__(16) __nv_bfloat16 As[128 * SSTR];
    __shared__ __align__(16) __nv_bfloat16 Bs[128 * SSTR];
    const int tid  = threadIdx.x;
    const int lane = tid & 31;
    const int wid  = tid >> 5;
    const int wm   = wid >> 1;
    const int wn   = wid & 1;
    const int m0   = blockIdx.y * 128;
    const int n0   = blockIdx.x * 128;
    const int r    = lane >> 2;
    const int cq   = (lane & 3) * 2;

    float acc[2][8][4];
#pragma unroll
    for (int mt = 0; mt < 2; mt++)
#pragma unroll
        for (int nt = 0; nt < 8; nt++)
#pragma unroll
            for (int u = 0; u < 4; u++) acc[mt][nt][u] = 0.f;

    const int lr = tid >> 1;
    const int lh = (tid & 1) * 8;
    const __nv_bfloat16* gA = g_A2 + (size_t)(m0 + lr) * KP + lh;
    const __nv_bfloat16* gB = g_B2T + (size_t)(n0 + lr) * KP + lh;

    uint4 av = *(const uint4*)gA;
    uint4 bv = *(const uint4*)gB;

    for (int k0 = 0; k0 < KP; k0 += 16) {
        __syncthreads();
        *(uint4*)&As[lr * SSTR + lh] = av;
        *(uint4*)&Bs[lr * SSTR + lh] = bv;
        __syncthreads();

        if (k0 + 16 < KP) {
            av = *(const uint4*)(gA + k0 + 16);
            bv = *(const uint4*)(gB + k0 + 16);
        }

        unsigned int bf0[8], bf1[8];
#pragma unroll
        for (int nt = 0; nt < 8; nt++) {
            int n = wn * 64 + nt * 8 + r;
            bf0[nt] = *(const unsigned int*)&Bs[n * SSTR + cq];
            bf1[nt] = *(const unsigned int*)&Bs[n * SSTR + cq + 8];
        }
#pragma unroll
        for (int mt = 0; mt < 2; mt++) {
            int m = wm * 32 + mt * 16 + r;
            unsigned int a0 = *(const unsigned int*)&As[m * SSTR + cq];
            unsigned int a1 = *(const unsigned int*)&As[(m + 8) * SSTR + cq];
            unsigned int a2 = *(const unsigned int*)&As[m * SSTR + cq + 8];
            unsigned int a3 = *(const unsigned int*)&As[(m + 8) * SSTR + cq + 8];
#pragma unroll
            for (int nt = 0; nt < 8; nt++) {
                asm volatile(
                    "mma.sync.aligned.m16n8k16.row.col.f32.bf16.bf16.f32 "
                    "{%0,%1,%2,%3}, {%4,%5,%6,%7}, {%8,%9}, {%0,%1,%2,%3};"
                    : "+f"(acc[mt][nt][0]), "+f"(acc[mt][nt][1]),
                      "+f"(acc[mt][nt][2]), "+f"(acc[mt][nt][3])
                    : "r"(a0), "r"(a1), "r"(a2), "r"(a3),
                      "r"(bf0[nt]), "r"(bf1[nt]));
            }
        }
    }

    // ---------------- fused epilogue ----------------
    const int nx = blockIdx.x;
    if (nx < 12) {
        const int region = nx >> 2;               // 0=q, 1=k, 2=v
        const int off    = region * 64;
        const int h      = (nx & 3) * 2 + wn;

#pragma unroll
        for (int mt = 0; mt < 2; mt++) {
            const int mA = m0 + wm * 32 + mt * 16 + r;
            const int mB = mA + 8;

            float sc0 = 1.f, sc1 = 1.f;
            if (region == 1) {
                float ss0 = 0.f, ss1 = 0.f;
#pragma unroll
                for (int nt = 0; nt < 8; nt++) {
                    ss0 = fmaf(acc[mt][nt][0], acc[mt][nt][0], ss0);
                    ss0 = fmaf(acc[mt][nt][1], acc[mt][nt][1], ss0);
                    ss1 = fmaf(acc[mt][nt][2], acc[mt][nt][2], ss1);
                    ss1 = fmaf(acc[mt][nt][3], acc[mt][nt][3], ss1);
                }
                ss0 += __shfl_xor_sync(0xffffffffu, ss0, 1);
                ss1 += __shfl_xor_sync(0xffffffffu, ss1, 1);
                ss0 += __shfl_xor_sync(0xffffffffu, ss0, 2);
                ss1 += __shfl_xor_sync(0xffffffffu, ss1, 2);
                sc0 = 1.0f / fmaxf(sqrtf(ss0), 1e-12f);
                sc1 = 1.0f / fmaxf(sqrtf(ss1), 1e-12f);
            }

            const int bA = mA >> 9, lA = mA & 511;
            const int bB = mB >> 9, lB = mB & 511;
            float* dA = g_pack + ((size_t)(bA * 8 + h) * 512 + lA) * PSTEP + off + cq;
            float* dB = g_pack + ((size_t)(bB * 8 + h) * 512 + lB) * PSTEP + off + cq;
#pragma unroll
            for (int nt = 0; nt < 8; nt++) {
                *(float2*)(dA + nt * 8) = make_float2(acc[mt][nt][0] * sc0,
                                                      acc[mt][nt][1] * sc0);
                *(float2*)(dB + nt * 8) = make_float2(acc[mt][nt][2] * sc1,
                                                      acc[mt][nt][3] * sc1);
            }
        }
    } else {
        // p tile: fused gate activations. cols cp = nt*8+cq < 24 (wn==0 only).
        if (wn == 0) {
#pragma unroll
            for (int mt = 0; mt < 2; mt++) {
                const int mA = m0 + wm * 32 + mt * 16 + r;
                const int mB = mA + 8;
                const int bA = mA >> 9, lA = mA & 511;
                const int bB = mB >> 9, lB = mB & 511;
#pragma unroll
                for (int nt = 0; nt < 3; nt++) {
                    const int cp = nt * 8 + cq;       // 0..22 even; cp+1 <= 23
                    const float b0 = bp[cp], b1 = bp[cp + 1];
#pragma unroll
                    for (int half = 0; half < 2; half++) {
                        const int cc   = cp + half;
                        const int slot = cc >> 3;     // 0=alpha,1=eta,2=theta
                        const int h    = cc & 7;
                        const float bb = half ? b1 : b0;
                        float pA = acc[mt][nt][half]     + bb;
                        float pB = acc[mt][nt][2 + half] + bb;
                        float gA_, gB_;
                        if (slot < 2) {
                            gA_ = 1.0f / (1.0f + expf(-pA));
                            gB_ = 1.0f / (1.0f + expf(-pB));
                        } else {
                            gA_ = (pA > 20.f) ? pA : log1pf(expf(pA));
                            gB_ = (pB > 20.f) ? pB : log1pf(expf(pB));
                        }
                        g_pack[((size_t)(bA * 8 + h) * 512 + lA) * PSTEP + 192 + slot] = gA_;
                        g_pack[((size_t)(bB * 8 + h) * 512 + lB) * PSTEP + 192 + slot] = gB_;
                    }
                }
            }
        }
    }
}

// ---------------------------------------------------------------------------
// Kernel 3: recurrence (r12-proven config, STG stores).
// grid = B*H*16 = 1024 CTAs x 64 threads (2048 warps).
// CTA handles 4 rows of one (b,h). Thread (r = t>>4, c = t&15) owns 4 cols.
// 4-deep register ring with prefetch distance 3 to cover L2/DRAM latency.
// ---------------------------------------------------------------------------
__global__ __launch_bounds__(64) void recurrence_kernel(const float* __restrict__ prev_state,
                                                        const float* __restrict__ prev_mom,
                                                        float* __restrict__ out) {
    const int bid = blockIdx.x;
    const int rb  = bid & 15;
    const int h   = (bid >> 4) & 7;
    const int b   = bid >> 7;
    const int t   = threadIdx.x;
    const int r = t >> 4, c = t & 15;
    const int gi = rb * 4 + r;                  // global state row in [0,64)

    float s[4], m[4];
    {
        const size_t off = ((size_t)((b * 8 + h) * 64 + gi)) * 64 + c * 4;
        *(float4*)&s[0] = *(const float4*)(prev_state + off);
        *(float4*)&m[0] = *(const float4*)(prev_mom + off);
    }

    const float* pbh = g_pack + (size_t)((b * 8 + h) * 512) * PSTEP;
    float* ro  = out + ((size_t)(b * 512) * 8 + h) * 64 + gi;
    float* ssq = out + OFF_S + ((size_t)(b * 512) * 8 + h) * 4096 + (size_t)gi * 64 + c * 4;
    float* msq = ssq + (OFF_M - OFF_S);

    // 4-deep prefetch ring (q, k, v, gates)
    float qb[4][4], kb[4][4], vb[4];
    float4 gb[4];
#pragma unroll
    for (int p = 0; p < 3; p++) {
        const float* sp = pbh + p * PSTEP;
        *(float4*)qb[p] = *(const float4*)(sp + c * 4);
        *(float4*)kb[p] = *(const float4*)(sp + 64 + c * 4);
        vb[p] = sp[128 + gi];
        gb[p] = *(const float4*)(sp + 192);
    }

#pragma unroll 4
    for (int l = 0; l < 512; ++l) {
        const int bi = l & 3;
        const int pi = (l + 3) & 3;
        const int pl = (l + 3 < 512) ? (l + 3) : 511;
        const float* sp = pbh + (size_t)pl * PSTEP;
        *(float4*)qb[pi] = *(const float4*)(sp + c * 4);
        *(float4*)kb[pi] = *(const float4*)(sp + 64 + c * 4);
        vb[pi] = sp[128 + gi];
        gb[pi] = *(const float4*)(sp + 192);

        // partial dot products over owned 4 columns
        float pv = 0.f, py = 0.f;
#pragma unroll
        for (int u = 0; u < 4; u++) {
            pv = fmaf(s[u], kb[bi][u], pv);
            py = fmaf(s[u], qb[bi][u], py);
        }
        // reduce over the 16 lanes of this row (pv/py chains interleave)
        pv += __shfl_xor_sync(0xffffffffu, pv, 1);
        py += __shfl_xor_sync(0xffffffffu, py, 1);
        pv += __shfl_xor_sync(0xffffffffu, pv, 2);
        py += __shfl_xor_sync(0xffffffffu, py, 2);
        pv += __shfl_xor_sync(0xffffffffu, pv, 4);
        py += __shfl_xor_sync(0xffffffffu, py, 4);
        pv += __shfl_xor_sync(0xffffffffu, pv, 8);
        py += __shfl_xor_sync(0xffffffffu, py, 8);

        if (c == 0) __stcs(ro + (size_t)l * 512, py);   // readout: PRE-update state

        const float d   = pv - vb[bi];
        const float td  = gb[bi].z * d;
        const float oma = 1.0f - gb[bi].x;
        const float e   = gb[bi].y;
#pragma unroll
        for (int u = 0; u < 4; u++) {
            m[u] = fmaf(e, m[u], -td * kb[bi][u]);   // eta*mom - theta*grad
            s[u] = fmaf(oma, s[u], m[u]);            // (1-alpha)*state + mom
        }

        __stcs((float4*)(ssq + (size_t)l * 32768), *(float4*)&s[0]);
        __stcs((float4*)(msq + (size_t)l * 32768), *(float4*)&m[0]);
    }
}

// ---------------------------------------------------------------------------
// Launch
// ---------------------------------------------------------------------------
extern "C" void kernel_launch(void* const* d_in, const int* in_sizes, int n_in,
                              void* d_out, int out_size) {
    const float* inputs   = (const float*)d_in[0];
    const float* Wq       = (const float*)d_in[1];
    const float* Wk       = (const float*)d_in[2];
    const float* Wv       = (const float*)d_in[3];
    const float* Wp       = (const float*)d_in[4];
    const float* bp       = (const float*)d_in[5];
    const float* prev_st  = (const float*)d_in[6];
    const float* prev_mom = (const float*)d_in[7];
    float* out = (float*)d_out;

    pack_a2_kernel<<<(NROWS * KP + 255) / 256, 256>>>(inputs);
    pack_b2t_kernel<<<dim3(NPAD / 32, D_ / 32), dim3(32, 8)>>>(Wq, Wk, Wv, Wp);
    mma_gemm_kernel<<<dim3(NPAD / 128, NROWS / 128), 256>>>(bp);
    recurrence_kernel<<<B_ * H_ * 16, 64>>>(prev_st, prev_mom, out);
}